// round 11
// baseline (speedup 1.0000x reference)
#include <cuda_runtime.h>
#include <math.h>
#include <stdint.h>

#define B 8
#define T 4096
#define D 256
#define H 50
#define HP 64
#define BM 128
#define BN 64
#define NT (T / BN)
#define SCALE 0.14142135623730951f
#define LOG2E 1.4426950408889634f

__device__ uint16_t g_q[B * T * HP];   // bf16, pre-scaled by SCALE*LOG2E
__device__ uint16_t g_k[B * T * HP];   // bf16
__device__ float    g_vt[B * HP * T];  // fp32, transposed [b][h][t]

__device__ __forceinline__ uint32_t smem_u32(const void* p) {
    uint32_t a;
    asm("{ .reg .u64 t; cvta.to.shared.u64 t, %1; cvt.u32.u64 %0, t; }" : "=r"(a) : "l"(p));
    return a;
}
__device__ __forceinline__ void ldsm4(uint32_t* r, uint32_t a) {
    asm volatile("ldmatrix.sync.aligned.m8n8.x4.shared.b16 {%0,%1,%2,%3}, [%4];"
        : "=r"(r[0]), "=r"(r[1]), "=r"(r[2]), "=r"(r[3]) : "r"(a));
}
__device__ __forceinline__ void mma_tf32(float* c, const uint32_t* a, uint32_t b0, uint32_t b1) {
    asm volatile("mma.sync.aligned.m16n8k8.row.col.f32.tf32.tf32.f32 "
        "{%0,%1,%2,%3},{%4,%5,%6,%7},{%8,%9},{%0,%1,%2,%3};"
        : "+f"(c[0]), "+f"(c[1]), "+f"(c[2]), "+f"(c[3])
        : "r"(a[0]), "r"(a[1]), "r"(a[2]), "r"(a[3]), "r"(b0), "r"(b1));
}
__device__ __forceinline__ void mma_bf16(float* c, const uint32_t* a, uint32_t b0, uint32_t b1) {
    asm volatile("mma.sync.aligned.m16n8k16.row.col.f32.bf16.bf16.f32 "
        "{%0,%1,%2,%3},{%4,%5,%6,%7},{%8,%9},{%0,%1,%2,%3};"
        : "+f"(c[0]), "+f"(c[1]), "+f"(c[2]), "+f"(c[3])
        : "r"(a[0]), "r"(a[1]), "r"(a[2]), "r"(a[3]), "r"(b0), "r"(b1));
}
__device__ __forceinline__ float to_tf32(float x) {
    uint32_t u;
    asm("cvt.rna.tf32.f32 %0, %1;" : "=r"(u) : "f"(x));
    return __uint_as_float(u);
}
__device__ __forceinline__ float ex2(float x) {
    float r;
    asm("ex2.approx.f32 %0, %1;" : "=f"(r) : "f"(x));
    return r;
}
__device__ __forceinline__ uint32_t pack_bf2(float lo, float hi) {
    uint32_t r;
    asm("cvt.rn.bf16x2.f32 %0, %1, %2;" : "=r"(r) : "f"(hi), "f"(lo));
    return r;
}
__device__ __forceinline__ void cpa16(uint32_t dst, const void* src) {
    asm volatile("cp.async.cg.shared.global [%0], [%1], 16;" :: "r"(dst), "l"(src));
}
#define CP_COMMIT() asm volatile("cp.async.commit_group;" ::: "memory")
#define CP_WAIT0()  asm volatile("cp.async.wait_group 0;" ::: "memory")

// ---------------------------------------------------------------------------
// Kernel 1: QKV projection (tf32 warp-MMA).
// 128 threads / 4 warps, 64 rows x 192 cols per CTA, grid = B*T/64 = 512.
// 3 CTAs/SM. Q scaled by SCALE*LOG2E -> bf16; K -> bf16; V -> g_vt fp32.
// ---------------------------------------------------------------------------
#define NQK 192
#define XST 36
#define WST 36

__global__ void __launch_bounds__(128, 3) qkv_mma(const float* __restrict__ x,
                                                  const float* __restrict__ w) {
    __shared__ float xs[64 * XST];     // 9.2 KB
    __shared__ float wt[NQK * WST];    // 27.6 KB
    const int tid  = threadIdx.x;
    const int lane = tid & 31;
    const int wp   = tid >> 5;
    const int r0   = blockIdx.x * 64;

    const uint32_t xs_b = smem_u32(xs);
    const uint32_t wt_b = smem_u32(wt);
    const uint32_t a_addr = xs_b
        + (wp * 16 + (lane & 7) + 8 * ((lane >> 3) & 1)) * (XST * 4)
        + (lane >> 4) * 16;
    const uint32_t b_addr = wt_b
        + ((lane & 7) + 8 * (lane >> 4)) * (WST * 4)
        + ((lane >> 3) & 1) * 16;

    float c[24][4];
    #pragma unroll
    for (int i = 0; i < 24; i++)
        #pragma unroll
        for (int e = 0; e < 4; e++) c[i][e] = 0.f;

    for (int k0 = 0; k0 < D; k0 += 32) {
        __syncthreads();
        // x chunk [64][32], tf32-rounded
        #pragma unroll
        for (int i = 0; i < 4; i++) {
            int idx = tid + i * 128;
            int r = idx >> 3, c4 = idx & 7;
            float4 v = *(const float4*)(x + (size_t)(r0 + r) * D + k0 + c4 * 4);
            float* dst = xs + r * XST + c4 * 4;
            dst[0] = to_tf32(v.x); dst[1] = to_tf32(v.y);
            dst[2] = to_tf32(v.z); dst[3] = to_tf32(v.w);
        }
        // w^T chunk [192][32]
        #pragma unroll
        for (int i = 0; i < 48; i++) {
            int idx = tid + i * 128;
            int n = idx >> 5, kc = idx & 31;
            int m = n >> 6, h = n & 63;
            float val = (h < H) ? w[m * (D * H) + (k0 + kc) * H + h] : 0.f;
            wt[n * WST + kc] = to_tf32(val);
        }
        __syncthreads();

        #pragma unroll
        for (int ks = 0; ks < 4; ks++) {
            uint32_t qa[4];
            ldsm4(qa, a_addr + ks * 32);
            #pragma unroll
            for (int np = 0; np < 12; np++) {
                uint32_t bb[4];
                ldsm4(bb, b_addr + np * (16 * WST * 4) + ks * 32);
                mma_tf32(c[2 * np],     qa, bb[0], bb[1]);
                mma_tf32(c[2 * np + 1], qa, bb[2], bb[3]);
            }
        }
    }

    const int pr = lane >> 2, pc = 2 * (lane & 3);
    const int row = r0 + wp * 16 + pr;
    const int bb_ = row >> 12;
    const int t_  = row & (T - 1);
    #pragma unroll
    for (int nt = 0; nt < 24; nt++) {
        int n = nt * 8 + pc;
        int m = n >> 6, h = n & 63;
        if (m == 2) {                       // V transposed, fp32 tf32-rounded
            float* vt = g_vt + ((size_t)bb_ * HP + h) * T + t_;
            vt[0]     = to_tf32(c[nt][0]);
            vt[T]     = to_tf32(c[nt][1]);
            vt[8]     = to_tf32(c[nt][2]);
            vt[T + 8] = to_tf32(c[nt][3]);
        } else {                            // Q (scale*log2e) / K packed bf16
            float s = (m == 0) ? (SCALE * LOG2E) : 1.f;
            uint16_t* dst = (m == 0) ? g_q : g_k;
            *(uint32_t*)(dst + (size_t)row * HP + h) =
                pack_bf2(c[nt][0] * s, c[nt][1] * s);
            *(uint32_t*)(dst + (size_t)(row + 8) * HP + h) =
                pack_bf2(c[nt][2] * s, c[nt][3] * s);
        }
    }
}

// ---------------------------------------------------------------------------
// Kernel 2: flash attention (R9 structure). S = QK^T bf16 (m16n8k16),
// p = 2^S via ex2 (log2e pre-folded into Q), PV in tf32.
// 128 threads / 4 warps, warp owns 32 q-rows; double-buffered cp.async.
// ---------------------------------------------------------------------------
#define KSTB 144
#define KBUFB (64 * KSTB)
#define VST 68
#define VBUF (64 * VST * 4)
#define KOFF 0
#define VOFF (2 * KBUFB)
#define SMEMSZ (VOFF + 2 * VBUF) // 53248

__device__ __forceinline__ void load_kv(uint32_t ksm_b, uint32_t vsm_b, int buf,
                                        int t, int b) {
    const int tid = threadIdx.x;
    const uint16_t* kg = g_k  + ((size_t)b * T + t * BN) * HP;
    const float*   vtg = g_vt + (size_t)b * HP * T + t * BN;
    const uint32_t kdst = ksm_b + buf * KBUFB;
    const uint32_t vdst = vsm_b + buf * VBUF;
    #pragma unroll
    for (int j = 0; j < 4; j++) {
        int i = tid + j * 128;
        int n = i >> 3, c = i & 7;
        cpa16(kdst + n * KSTB + c * 16, kg + n * HP + c * 8);
    }
    #pragma unroll
    for (int j = 0; j < 8; j++) {
        int i = tid + j * 128;
        int n = i >> 4, c4 = i & 15;
        cpa16(vdst + n * (VST * 4) + c4 * 16, vtg + (size_t)n * T + c4 * 4);
    }
}

__global__ void __launch_bounds__(128, 2) attn_tc(float* __restrict__ out) {
    extern __shared__ char smc[];
    const int tid  = threadIdx.x;
    const int lane = tid & 31;
    const int w    = tid >> 5;
    const int tig  = lane & 3;
    const int pr   = lane >> 2;

    const int b = blockIdx.x >> 5;
    const int row_blk = blockIdx.x * BM;

    const uint32_t ksm_b = smem_u32(smc + KOFF);
    const uint32_t vsm_b = smem_u32(smc + VOFF);
    const uint32_t kb_off = ((lane & 7) + 8 * (lane >> 4)) * KSTB
                          + ((lane >> 3) & 1) * 16;
    const uint32_t vb_off = ((lane & 7) + 8 * (lane >> 4)) * (VST * 4)
                          + ((lane >> 3) & 1) * 16;

    // ---- stage Q (bf16) through K region, grab A-frags ----
    {
        const uint16_t* qb = g_q + (size_t)(row_blk + tid) * HP;
        char* dst = smc + tid * KSTB;
        #pragma unroll
        for (int j = 0; j < 8; j++)
            *(float4*)(dst + j * 16) = *(const float4*)(qb + j * 8);
    }
    __syncthreads();
    uint32_t qa[2][4][4];
    {
        const uint32_t a_addr = ksm_b
            + (w * 32 + (lane & 7) + 8 * ((lane >> 3) & 1)) * KSTB
            + (lane >> 4) * 16;
        #pragma unroll
        for (int msub = 0; msub < 2; msub++)
            #pragma unroll
            for (int kc = 0; kc < 4; kc++)
                ldsm4(qa[msub][kc], a_addr + msub * (16 * KSTB) + kc * 32);
    }
    __syncthreads();

    float z[2][7][4];
    #pragma unroll
    for (int i = 0; i < 2; i++)
        #pragma unroll
        for (int j = 0; j < 7; j++)
            #pragma unroll
            for (int e = 0; e < 4; e++) z[i][j][e] = 0.f;
    float lacc[2][2] = {{0.f, 0.f}, {0.f, 0.f}};

    load_kv(ksm_b, vsm_b, 0, 0, b);
    CP_COMMIT();
    CP_WAIT0();
    __syncthreads();

    const int srcA = (lane & 28) | (tig >> 1);
    const int srcB = srcA + 2;
    const bool odd = (tig & 1);

    for (int t = 0; t < NT; t++) {
        const int cur = t & 1;
        if (t + 1 < NT) load_kv(ksm_b, vsm_b, cur ^ 1, t + 1, b);
        CP_COMMIT();

        const uint32_t kb_addr = ksm_b + cur * KBUFB + kb_off;
        const uint32_t vb_addr = vsm_b + cur * VBUF + vb_off;

        // ---- S = Q K^T (bf16 k16) ----
        float sc[2][8][4];
        #pragma unroll
        for (int i = 0; i < 2; i++)
            #pragma unroll
            for (int j = 0; j < 8; j++)
                #pragma unroll
                for (int e = 0; e < 4; e++) sc[i][j][e] = 0.f;

        #pragma unroll
        for (int kc = 0; kc < 4; kc++) {
            #pragma unroll
            for (int nb = 0; nb < 4; nb++) {
                uint32_t bb[4];
                ldsm4(bb, kb_addr + nb * (16 * KSTB) + kc * 32);
                #pragma unroll
                for (int msub = 0; msub < 2; msub++) {
                    mma_bf16(sc[msub][2 * nb],     qa[msub][kc], bb[0], bb[1]);
                    mma_bf16(sc[msub][2 * nb + 1], qa[msub][kc], bb[2], bb[3]);
                }
            }
        }

        // ---- softmax: p = 2^S (log2e folded into Q); scores bounded ----
        #pragma unroll
        for (int msub = 0; msub < 2; msub++)
            #pragma unroll
            for (int nt = 0; nt < 8; nt++) {
                float p0 = ex2(sc[msub][nt][0]);
                float p1 = ex2(sc[msub][nt][1]);
                float p2 = ex2(sc[msub][nt][2]);
                float p3 = ex2(sc[msub][nt][3]);
                lacc[msub][0] += p0 + p1;
                lacc[msub][1] += p2 + p3;
                sc[msub][nt][0] = to_tf32(p0); sc[msub][nt][1] = to_tf32(p1);
                sc[msub][nt][2] = to_tf32(p2); sc[msub][nt][3] = to_tf32(p3);
            }

        // ---- Z += P V^T (tf32): P A-frags via quad-shfl transpose ----
        #pragma unroll
        for (int ks = 0; ks < 8; ks++) {
            uint32_t pa[2][4];
            #pragma unroll
            for (int msub = 0; msub < 2; msub++) {
                float e0 = __shfl_sync(0xffffffffu, sc[msub][ks][0], srcA);
                float e1 = __shfl_sync(0xffffffffu, sc[msub][ks][1], srcA);
                pa[msub][0] = __float_as_uint(odd ? e1 : e0);
                float e2 = __shfl_sync(0xffffffffu, sc[msub][ks][2], srcA);
                float e3 = __shfl_sync(0xffffffffu, sc[msub][ks][3], srcA);
                pa[msub][1] = __float_as_uint(odd ? e3 : e2);
                float f0 = __shfl_sync(0xffffffffu, sc[msub][ks][0], srcB);
                float f1 = __shfl_sync(0xffffffffu, sc[msub][ks][1], srcB);
                pa[msub][2] = __float_as_uint(odd ? f1 : f0);
                float f2 = __shfl_sync(0xffffffffu, sc[msub][ks][2], srcB);
                float f3 = __shfl_sync(0xffffffffu, sc[msub][ks][3], srcB);
                pa[msub][3] = __float_as_uint(odd ? f3 : f2);
            }
            #pragma unroll
            for (int np = 0; np < 4; np++) {
                uint32_t bb[4];
                ldsm4(bb, vb_addr + np * (16 * VST * 4) + ks * 32);
                #pragma unroll
                for (int msub = 0; msub < 2; msub++) {
                    mma_tf32(z[msub][2 * np], pa[msub], bb[0], bb[1]);
                    if (np < 3)
                        mma_tf32(z[msub][2 * np + 1], pa[msub], bb[2], bb[3]);
                }
            }
        }

        CP_WAIT0();
        __syncthreads();
    }

    // ---- l reduction within quad; output ----
    #pragma unroll
    for (int msub = 0; msub < 2; msub++) {
        float l0 = lacc[msub][0], l1 = lacc[msub][1];
        l0 += __shfl_xor_sync(0xffffffffu, l0, 1);
        l0 += __shfl_xor_sync(0xffffffffu, l0, 2);
        l1 += __shfl_xor_sync(0xffffffffu, l1, 1);
        l1 += __shfl_xor_sync(0xffffffffu, l1, 2);
        const float il0 = 1.f / l0;
        const float il1 = 1.f / l1;

        const int pc = 2 * tig;
        const int m0 = row_blk + w * 32 + msub * 16 + pr;
        #pragma unroll
        for (int nt = 0; nt < 7; nt++) {
            int h = nt * 8 + pc;
            if (h <= 48) {
                *(float2*)(out + (size_t)m0 * H + h) =
                    make_float2(z[msub][nt][0] * il0, z[msub][nt][1] * il0);
                *(float2*)(out + (size_t)(m0 + 8) * H + h) =
                    make_float2(z[msub][nt][2] * il1, z[msub][nt][3] * il1);
            }
        }
    }
}

// ---------------------------------------------------------------------------
extern "C" void kernel_launch(void* const* d_in, const int* in_sizes, int n_in,
                              void* d_out, int out_size) {
    const float* x = (const float*)d_in[0];
    const float* w = (const float*)d_in[1];
    float* out = (float*)d_out;

    static int configured = 0;
    if (!configured) {
        cudaFuncSetAttribute(attn_tc, cudaFuncAttributeMaxDynamicSharedMemorySize, SMEMSZ);
        configured = 1;
    }

    qkv_mma<<<(B * T) / 64, 128>>>(x, w);
    attn_tc<<<(B * T) / BM, 128, SMEMSZ>>>(out);
}

// round 12
// speedup vs baseline: 1.2798x; 1.2798x over previous
#include <cuda_runtime.h>
#include <math.h>
#include <stdint.h>

#define B 8
#define T 4096
#define D 256
#define H 50
#define HP 64
#define BM 128
#define BN 64
#define NT (T / BN)
#define SCALE 0.14142135623730951f
#define LOG2E 1.4426950408889634f

__device__ uint16_t g_q[B * T * HP];   // bf16, pre-scaled by SCALE*LOG2E
__device__ uint16_t g_k[B * T * HP];   // bf16
__device__ float    g_vt[B * HP * T];  // fp32, transposed [b][h][t]
__device__ float    g_wt[192 * D];     // w^T, tf32-rounded: [n=m*64+h][k]

__device__ __forceinline__ uint32_t smem_u32(const void* p) {
    uint32_t a;
    asm("{ .reg .u64 t; cvta.to.shared.u64 t, %1; cvt.u32.u64 %0, t; }" : "=r"(a) : "l"(p));
    return a;
}
__device__ __forceinline__ void ldsm4(uint32_t* r, uint32_t a) {
    asm volatile("ldmatrix.sync.aligned.m8n8.x4.shared.b16 {%0,%1,%2,%3}, [%4];"
        : "=r"(r[0]), "=r"(r[1]), "=r"(r[2]), "=r"(r[3]) : "r"(a));
}
__device__ __forceinline__ void mma_tf32(float* c, const uint32_t* a, uint32_t b0, uint32_t b1) {
    asm volatile("mma.sync.aligned.m16n8k8.row.col.f32.tf32.tf32.f32 "
        "{%0,%1,%2,%3},{%4,%5,%6,%7},{%8,%9},{%0,%1,%2,%3};"
        : "+f"(c[0]), "+f"(c[1]), "+f"(c[2]), "+f"(c[3])
        : "r"(a[0]), "r"(a[1]), "r"(a[2]), "r"(a[3]), "r"(b0), "r"(b1));
}
__device__ __forceinline__ void mma_bf16(float* c, const uint32_t* a, uint32_t b0, uint32_t b1) {
    asm volatile("mma.sync.aligned.m16n8k16.row.col.f32.bf16.bf16.f32 "
        "{%0,%1,%2,%3},{%4,%5,%6,%7},{%8,%9},{%0,%1,%2,%3};"
        : "+f"(c[0]), "+f"(c[1]), "+f"(c[2]), "+f"(c[3])
        : "r"(a[0]), "r"(a[1]), "r"(a[2]), "r"(a[3]), "r"(b0), "r"(b1));
}
__device__ __forceinline__ float to_tf32(float x) {
    uint32_t u;
    asm("cvt.rna.tf32.f32 %0, %1;" : "=r"(u) : "f"(x));
    return __uint_as_float(u);
}
__device__ __forceinline__ float ex2(float x) {
    float r;
    asm("ex2.approx.f32 %0, %1;" : "=f"(r) : "f"(x));
    return r;
}
__device__ __forceinline__ uint32_t pack_bf2(float lo, float hi) {
    uint32_t r;
    asm("cvt.rn.bf16x2.f32 %0, %1, %2;" : "=r"(r) : "f"(hi), "f"(lo));
    return r;
}
__device__ __forceinline__ void cpa16(uint32_t dst, const void* src) {
    asm volatile("cp.async.cg.shared.global [%0], [%1], 16;" :: "r"(dst), "l"(src));
}
#define CP_COMMIT() asm volatile("cp.async.commit_group;" ::: "memory")
#define CP_WAIT0()  asm volatile("cp.async.wait_group 0;" ::: "memory")

// ---------------------------------------------------------------------------
// Kernel 0: transpose + tf32-round w -> g_wt[192][256]
// ---------------------------------------------------------------------------
__global__ void __launch_bounds__(256) wtrans(const float* __restrict__ w) {
    int idx = blockIdx.x * 256 + threadIdx.x;   // 192*256
    int n = idx >> 8;
    int k = idx & 255;
    int m = n >> 6, h = n & 63;
    g_wt[idx] = (h < H) ? to_tf32(w[m * (D * H) + k * H + h]) : 0.f;
}

// ---------------------------------------------------------------------------
// Kernel 1: QKV projection (tf32 warp-MMA), double-buffered pipeline.
// 256 threads / 8 warps, 128 rows x 192 cols, grid 256. w^T via cp.async.
// ---------------------------------------------------------------------------
#define NQK 192
#define XST 36
#define WST 36
#define XSB (128 * XST * 4)      // 18432 B per x buffer
#define WTB (NQK * WST * 4)      // 27648 B per w buffer
#define QSMEM (2 * XSB + 2 * WTB) // 92160 B

__device__ __forceinline__ void qkv_stage(char* smc, uint32_t sb, int buf,
                                          const float* __restrict__ x,
                                          int r0, int k0) {
    const int tid = threadIdx.x;
    // x chunk [128][32], rna-rounded, STS
    float* xs = (float*)(smc + buf * XSB);
    #pragma unroll
    for (int i = 0; i < 4; i++) {
        int idx = tid + i * 256;
        int r = idx >> 3, c4 = idx & 7;
        float4 v = *(const float4*)(x + (size_t)(r0 + r) * D + k0 + c4 * 4);
        float* dst = xs + r * XST + c4 * 4;
        dst[0] = to_tf32(v.x); dst[1] = to_tf32(v.y);
        dst[2] = to_tf32(v.z); dst[3] = to_tf32(v.w);
    }
    // w^T chunk [192][32] via cp.async (pre-rounded in g_wt)
    const uint32_t wdst = sb + 2 * XSB + buf * WTB;
    #pragma unroll
    for (int i = 0; i < 6; i++) {
        int idx = tid + i * 256;
        int n = idx >> 3, c = idx & 7;
        cpa16(wdst + n * (WST * 4) + c * 16, g_wt + (size_t)n * D + k0 + c * 4);
    }
}

__global__ void __launch_bounds__(256) qkv_mma(const float* __restrict__ x) {
    extern __shared__ char smc[];
    const uint32_t sb = smem_u32(smc);
    const int tid  = threadIdx.x;
    const int lane = tid & 31;
    const int wp   = tid >> 5;
    const int r0   = blockIdx.x * 128;

    const uint32_t a_base = sb
        + (wp * 16 + (lane & 7) + 8 * ((lane >> 3) & 1)) * (XST * 4)
        + (lane >> 4) * 16;
    const uint32_t b_base = sb + 2 * XSB
        + ((lane & 7) + 8 * (lane >> 4)) * (WST * 4)
        + ((lane >> 3) & 1) * 16;

    float c[24][4];
    #pragma unroll
    for (int i = 0; i < 24; i++)
        #pragma unroll
        for (int e = 0; e < 4; e++) c[i][e] = 0.f;

    qkv_stage(smc, sb, 0, x, r0, 0);
    CP_COMMIT();
    CP_WAIT0();
    __syncthreads();

    for (int i = 0; i < 8; i++) {
        const int cur = i & 1;
        if (i < 7) {
            qkv_stage(smc, sb, cur ^ 1, x, r0, (i + 1) * 32);
            CP_COMMIT();
        }

        const uint32_t a_addr = a_base + cur * XSB;
        const uint32_t b_addr = b_base + cur * WTB;
        #pragma unroll
        for (int ks = 0; ks < 4; ks++) {
            uint32_t qa[4];
            ldsm4(qa, a_addr + ks * 32);
            #pragma unroll
            for (int np = 0; np < 12; np++) {
                uint32_t bb[4];
                ldsm4(bb, b_addr + np * (16 * WST * 4) + ks * 32);
                mma_tf32(c[2 * np],     qa, bb[0], bb[1]);
                mma_tf32(c[2 * np + 1], qa, bb[2], bb[3]);
            }
        }

        CP_WAIT0();
        __syncthreads();
    }

    const int pr = lane >> 2, pc = 2 * (lane & 3);
    const int row = r0 + wp * 16 + pr;
    const int bb_ = row >> 12;
    const int t_  = row & (T - 1);
    #pragma unroll
    for (int nt = 0; nt < 24; nt++) {
        int n = nt * 8 + pc;
        int m = n >> 6, h = n & 63;
        if (m == 2) {                       // V transposed, fp32 tf32-rounded
            float* vt = g_vt + ((size_t)bb_ * HP + h) * T + t_;
            vt[0]     = to_tf32(c[nt][0]);
            vt[T]     = to_tf32(c[nt][1]);
            vt[8]     = to_tf32(c[nt][2]);
            vt[T + 8] = to_tf32(c[nt][3]);
        } else {                            // Q (scale*log2e) / K packed bf16
            float s = (m == 0) ? (SCALE * LOG2E) : 1.f;
            uint16_t* dst = (m == 0) ? g_q : g_k;
            *(uint32_t*)(dst + (size_t)row * HP + h) =
                pack_bf2(c[nt][0] * s, c[nt][1] * s);
            *(uint32_t*)(dst + (size_t)(row + 8) * HP + h) =
                pack_bf2(c[nt][2] * s, c[nt][3] * s);
        }
    }
}

// ---------------------------------------------------------------------------
// Kernel 2: flash attention (unchanged from R11 best). S = QK^T bf16,
// p = 2^S via ex2 (log2e folded into Q), PV in tf32.
// ---------------------------------------------------------------------------
#define KSTB 144
#define KBUFB (64 * KSTB)
#define VST 68
#define VBUF (64 * VST * 4)
#define KOFF 0
#define VOFF (2 * KBUFB)
#define SMEMSZ (VOFF + 2 * VBUF) // 53248

__device__ __forceinline__ void load_kv(uint32_t ksm_b, uint32_t vsm_b, int buf,
                                        int t, int b) {
    const int tid = threadIdx.x;
    const uint16_t* kg = g_k  + ((size_t)b * T + t * BN) * HP;
    const float*   vtg = g_vt + (size_t)b * HP * T + t * BN;
    const uint32_t kdst = ksm_b + buf * KBUFB;
    const uint32_t vdst = vsm_b + buf * VBUF;
    #pragma unroll
    for (int j = 0; j < 4; j++) {
        int i = tid + j * 128;
        int n = i >> 3, c = i & 7;
        cpa16(kdst + n * KSTB + c * 16, kg + n * HP + c * 8);
    }
    #pragma unroll
    for (int j = 0; j < 8; j++) {
        int i = tid + j * 128;
        int n = i >> 4, c4 = i & 15;
        cpa16(vdst + n * (VST * 4) + c4 * 16, vtg + (size_t)n * T + c4 * 4);
    }
}

__global__ void __launch_bounds__(128, 2) attn_tc(float* __restrict__ out) {
    extern __shared__ char smc[];
    const int tid  = threadIdx.x;
    const int lane = tid & 31;
    const int w    = tid >> 5;
    const int tig  = lane & 3;
    const int pr   = lane >> 2;

    const int b = blockIdx.x >> 5;
    const int row_blk = blockIdx.x * BM;

    const uint32_t ksm_b = smem_u32(smc + KOFF);
    const uint32_t vsm_b = smem_u32(smc + VOFF);
    const uint32_t kb_off = ((lane & 7) + 8 * (lane >> 4)) * KSTB
                          + ((lane >> 3) & 1) * 16;
    const uint32_t vb_off = ((lane & 7) + 8 * (lane >> 4)) * (VST * 4)
                          + ((lane >> 3) & 1) * 16;

    // ---- stage Q (bf16) through K region, grab A-frags ----
    {
        const uint16_t* qb = g_q + (size_t)(row_blk + tid) * HP;
        char* dst = smc + tid * KSTB;
        #pragma unroll
        for (int j = 0; j < 8; j++)
            *(float4*)(dst + j * 16) = *(const float4*)(qb + j * 8);
    }
    __syncthreads();
    uint32_t qa[2][4][4];
    {
        const uint32_t a_addr = ksm_b
            + (w * 32 + (lane & 7) + 8 * ((lane >> 3) & 1)) * KSTB
            + (lane >> 4) * 16;
        #pragma unroll
        for (int msub = 0; msub < 2; msub++)
            #pragma unroll
            for (int kc = 0; kc < 4; kc++)
                ldsm4(qa[msub][kc], a_addr + msub * (16 * KSTB) + kc * 32);
    }
    __syncthreads();

    float z[2][7][4];
    #pragma unroll
    for (int i = 0; i < 2; i++)
        #pragma unroll
        for (int j = 0; j < 7; j++)
            #pragma unroll
            for (int e = 0; e < 4; e++) z[i][j][e] = 0.f;
    float lacc[2][2] = {{0.f, 0.f}, {0.f, 0.f}};

    load_kv(ksm_b, vsm_b, 0, 0, b);
    CP_COMMIT();
    CP_WAIT0();
    __syncthreads();

    const int srcA = (lane & 28) | (tig >> 1);
    const int srcB = srcA + 2;
    const bool odd = (tig & 1);

    for (int t = 0; t < NT; t++) {
        const int cur = t & 1;
        if (t + 1 < NT) load_kv(ksm_b, vsm_b, cur ^ 1, t + 1, b);
        CP_COMMIT();

        const uint32_t kb_addr = ksm_b + cur * KBUFB + kb_off;
        const uint32_t vb_addr = vsm_b + cur * VBUF + vb_off;

        // ---- S = Q K^T (bf16 k16) ----
        float sc[2][8][4];
        #pragma unroll
        for (int i = 0; i < 2; i++)
            #pragma unroll
            for (int j = 0; j < 8; j++)
                #pragma unroll
                for (int e = 0; e < 4; e++) sc[i][j][e] = 0.f;

        #pragma unroll
        for (int kc = 0; kc < 4; kc++) {
            #pragma unroll
            for (int nb = 0; nb < 4; nb++) {
                uint32_t bb[4];
                ldsm4(bb, kb_addr + nb * (16 * KSTB) + kc * 32);
                #pragma unroll
                for (int msub = 0; msub < 2; msub++) {
                    mma_bf16(sc[msub][2 * nb],     qa[msub][kc], bb[0], bb[1]);
                    mma_bf16(sc[msub][2 * nb + 1], qa[msub][kc], bb[2], bb[3]);
                }
            }
        }

        // ---- softmax: p = 2^S ----
        #pragma unroll
        for (int msub = 0; msub < 2; msub++)
            #pragma unroll
            for (int nt = 0; nt < 8; nt++) {
                float p0 = ex2(sc[msub][nt][0]);
                float p1 = ex2(sc[msub][nt][1]);
                float p2 = ex2(sc[msub][nt][2]);
                float p3 = ex2(sc[msub][nt][3]);
                lacc[msub][0] += p0 + p1;
                lacc[msub][1] += p2 + p3;
                sc[msub][nt][0] = to_tf32(p0); sc[msub][nt][1] = to_tf32(p1);
                sc[msub][nt][2] = to_tf32(p2); sc[msub][nt][3] = to_tf32(p3);
            }

        // ---- Z += P V^T (tf32): P A-frags via quad-shfl transpose ----
        #pragma unroll
        for (int ks = 0; ks < 8; ks++) {
            uint32_t pa[2][4];
            #pragma unroll
            for (int msub = 0; msub < 2; msub++) {
                float e0 = __shfl_sync(0xffffffffu, sc[msub][ks][0], srcA);
                float e1 = __shfl_sync(0xffffffffu, sc[msub][ks][1], srcA);
                pa[msub][0] = __float_as_uint(odd ? e1 : e0);
                float e2 = __shfl_sync(0xffffffffu, sc[msub][ks][2], srcA);
                float e3 = __shfl_sync(0xffffffffu, sc[msub][ks][3], srcA);
                pa[msub][1] = __float_as_uint(odd ? e3 : e2);
                float f0 = __shfl_sync(0xffffffffu, sc[msub][ks][0], srcB);
                float f1 = __shfl_sync(0xffffffffu, sc[msub][ks][1], srcB);
                pa[msub][2] = __float_as_uint(odd ? f1 : f0);
                float f2 = __shfl_sync(0xffffffffu, sc[msub][ks][2], srcB);
                float f3 = __shfl_sync(0xffffffffu, sc[msub][ks][3], srcB);
                pa[msub][3] = __float_as_uint(odd ? f3 : f2);
            }
            #pragma unroll
            for (int np = 0; np < 4; np++) {
                uint32_t bb[4];
                ldsm4(bb, vb_addr + np * (16 * VST * 4) + ks * 32);
                #pragma unroll
                for (int msub = 0; msub < 2; msub++) {
                    mma_tf32(z[msub][2 * np], pa[msub], bb[0], bb[1]);
                    if (np < 3)
                        mma_tf32(z[msub][2 * np + 1], pa[msub], bb[2], bb[3]);
                }
            }
        }

        CP_WAIT0();
        __syncthreads();
    }

    // ---- l reduction within quad; output ----
    #pragma unroll
    for (int msub = 0; msub < 2; msub++) {
        float l0 = lacc[msub][0], l1 = lacc[msub][1];
        l0 += __shfl_xor_sync(0xffffffffu, l0, 1);
        l0 += __shfl_xor_sync(0xffffffffu, l0, 2);
        l1 += __shfl_xor_sync(0xffffffffu, l1, 1);
        l1 += __shfl_xor_sync(0xffffffffu, l1, 2);
        const float il0 = 1.f / l0;
        const float il1 = 1.f / l1;

        const int pc = 2 * tig;
        const int m0 = row_blk + w * 32 + msub * 16 + pr;
        #pragma unroll
        for (int nt = 0; nt < 7; nt++) {
            int h = nt * 8 + pc;
            if (h <= 48) {
                *(float2*)(out + (size_t)m0 * H + h) =
                    make_float2(z[msub][nt][0] * il0, z[msub][nt][1] * il0);
                *(float2*)(out + (size_t)(m0 + 8) * H + h) =
                    make_float2(z[msub][nt][2] * il1, z[msub][nt][3] * il1);
            }
        }
    }
}

// ---------------------------------------------------------------------------
extern "C" void kernel_launch(void* const* d_in, const int* in_sizes, int n_in,
                              void* d_out, int out_size) {
    const float* x = (const float*)d_in[0];
    const float* w = (const float*)d_in[1];
    float* out = (float*)d_out;

    static int configured = 0;
    if (!configured) {
        cudaFuncSetAttribute(attn_tc, cudaFuncAttributeMaxDynamicSharedMemorySize, SMEMSZ);
        cudaFuncSetAttribute(qkv_mma, cudaFuncAttributeMaxDynamicSharedMemorySize, QSMEM);
        configured = 1;
    }

    wtrans<<<NQK, 256>>>(w);
    qkv_mma<<<(B * T) / 128, 256, QSMEM>>>(x);
    attn_tc<<<(B * T) / BM, 128, SMEMSZ>>>(out);
}

// round 13
// speedup vs baseline: 1.8671x; 1.4589x over previous
#include <cuda_runtime.h>
#include <math.h>
#include <stdint.h>

#define B 8
#define T 4096
#define D 256
#define H 50
#define HP 64
#define BM 128
#define BN 64
#define NT (T / BN)
#define SCALE 0.14142135623730951f
#define LOG2E 1.4426950408889634f

__device__ uint16_t g_q[B * T * HP];   // bf16, pre-scaled by SCALE*LOG2E
__device__ uint16_t g_k[B * T * HP];   // bf16
__device__ uint16_t g_vt[B * HP * T];  // fp16, transposed [b][h][t]
__device__ float    g_wt[192 * D];     // w^T, tf32-rounded: [n=m*64+h][k]

__device__ __forceinline__ uint32_t smem_u32(const void* p) {
    uint32_t a;
    asm("{ .reg .u64 t; cvta.to.shared.u64 t, %1; cvt.u32.u64 %0, t; }" : "=r"(a) : "l"(p));
    return a;
}
__device__ __forceinline__ void ldsm4(uint32_t* r, uint32_t a) {
    asm volatile("ldmatrix.sync.aligned.m8n8.x4.shared.b16 {%0,%1,%2,%3}, [%4];"
        : "=r"(r[0]), "=r"(r[1]), "=r"(r[2]), "=r"(r[3]) : "r"(a));
}
__device__ __forceinline__ void mma_tf32(float* c, const uint32_t* a, uint32_t b0, uint32_t b1) {
    asm volatile("mma.sync.aligned.m16n8k8.row.col.f32.tf32.tf32.f32 "
        "{%0,%1,%2,%3},{%4,%5,%6,%7},{%8,%9},{%0,%1,%2,%3};"
        : "+f"(c[0]), "+f"(c[1]), "+f"(c[2]), "+f"(c[3])
        : "r"(a[0]), "r"(a[1]), "r"(a[2]), "r"(a[3]), "r"(b0), "r"(b1));
}
__device__ __forceinline__ void mma_bf16(float* c, const uint32_t* a, uint32_t b0, uint32_t b1) {
    asm volatile("mma.sync.aligned.m16n8k16.row.col.f32.bf16.bf16.f32 "
        "{%0,%1,%2,%3},{%4,%5,%6,%7},{%8,%9},{%0,%1,%2,%3};"
        : "+f"(c[0]), "+f"(c[1]), "+f"(c[2]), "+f"(c[3])
        : "r"(a[0]), "r"(a[1]), "r"(a[2]), "r"(a[3]), "r"(b0), "r"(b1));
}
__device__ __forceinline__ void mma_f16(float* c, const uint32_t* a, uint32_t b0, uint32_t b1) {
    asm volatile("mma.sync.aligned.m16n8k16.row.col.f32.f16.f16.f32 "
        "{%0,%1,%2,%3},{%4,%5,%6,%7},{%8,%9},{%0,%1,%2,%3};"
        : "+f"(c[0]), "+f"(c[1]), "+f"(c[2]), "+f"(c[3])
        : "r"(a[0]), "r"(a[1]), "r"(a[2]), "r"(a[3]), "r"(b0), "r"(b1));
}
__device__ __forceinline__ float to_tf32(float x) {
    uint32_t u;
    asm("cvt.rna.tf32.f32 %0, %1;" : "=r"(u) : "f"(x));
    return __uint_as_float(u);
}
__device__ __forceinline__ float ex2(float x) {
    float r;
    asm("ex2.approx.f32 %0, %1;" : "=f"(r) : "f"(x));
    return r;
}
__device__ __forceinline__ uint32_t pack_bf2(float lo, float hi) {
    uint32_t r;
    asm("cvt.rn.bf16x2.f32 %0, %1, %2;" : "=r"(r) : "f"(hi), "f"(lo));
    return r;
}
__device__ __forceinline__ uint32_t pack_h2(float lo, float hi) {
    uint32_t r;
    asm("cvt.rn.f16x2.f32 %0, %1, %2;" : "=r"(r) : "f"(hi), "f"(lo));
    return r;
}
__device__ __forceinline__ uint16_t f2h(float x) {
    uint16_t u;
    asm("cvt.rn.f16.f32 %0, %1;" : "=h"(u) : "f"(x));
    return u;
}
__device__ __forceinline__ void cpa16(uint32_t dst, const void* src) {
    asm volatile("cp.async.cg.shared.global [%0], [%1], 16;" :: "r"(dst), "l"(src));
}
#define CP_COMMIT() asm volatile("cp.async.commit_group;" ::: "memory")
#define CP_WAIT0()  asm volatile("cp.async.wait_group 0;" ::: "memory")

// ---------------------------------------------------------------------------
// Kernel 0: transpose + tf32-round w -> g_wt[192][256]
// ---------------------------------------------------------------------------
__global__ void __launch_bounds__(256) wtrans(const float* __restrict__ w) {
    int idx = blockIdx.x * 256 + threadIdx.x;
    int n = idx >> 8;
    int k = idx & 255;
    int m = n >> 6, h = n & 63;
    g_wt[idx] = (h < H) ? to_tf32(w[m * (D * H) + k * H + h]) : 0.f;
}

// ---------------------------------------------------------------------------
// Kernel 1: QKV projection (tf32 warp-MMA), double-buffered (R12 verified).
// ---------------------------------------------------------------------------
#define NQK 192
#define XST 36
#define WST 36
#define XSB (128 * XST * 4)
#define WTB (NQK * WST * 4)
#define QSMEM (2 * XSB + 2 * WTB) // 92160

__device__ __forceinline__ void qkv_stage(char* smc, uint32_t sb, int buf,
                                          const float* __restrict__ x,
                                          int r0, int k0) {
    const int tid = threadIdx.x;
    float* xs = (float*)(smc + buf * XSB);
    #pragma unroll
    for (int i = 0; i < 4; i++) {
        int idx = tid + i * 256;
        int r = idx >> 3, c4 = idx & 7;
        float4 v = *(const float4*)(x + (size_t)(r0 + r) * D + k0 + c4 * 4);
        float* dst = xs + r * XST + c4 * 4;
        dst[0] = to_tf32(v.x); dst[1] = to_tf32(v.y);
        dst[2] = to_tf32(v.z); dst[3] = to_tf32(v.w);
    }
    const uint32_t wdst = sb + 2 * XSB + buf * WTB;
    #pragma unroll
    for (int i = 0; i < 6; i++) {
        int idx = tid + i * 256;
        int n = idx >> 3, c = idx & 7;
        cpa16(wdst + n * (WST * 4) + c * 16, g_wt + (size_t)n * D + k0 + c * 4);
    }
}

__global__ void __launch_bounds__(256) qkv_mma(const float* __restrict__ x) {
    extern __shared__ char smc[];
    const uint32_t sb = smem_u32(smc);
    const int tid  = threadIdx.x;
    const int lane = tid & 31;
    const int wp   = tid >> 5;
    const int r0   = blockIdx.x * 128;

    const uint32_t a_base = sb
        + (wp * 16 + (lane & 7) + 8 * ((lane >> 3) & 1)) * (XST * 4)
        + (lane >> 4) * 16;
    const uint32_t b_base = sb + 2 * XSB
        + ((lane & 7) + 8 * (lane >> 4)) * (WST * 4)
        + ((lane >> 3) & 1) * 16;

    float c[24][4];
    #pragma unroll
    for (int i = 0; i < 24; i++)
        #pragma unroll
        for (int e = 0; e < 4; e++) c[i][e] = 0.f;

    qkv_stage(smc, sb, 0, x, r0, 0);
    CP_COMMIT();
    CP_WAIT0();
    __syncthreads();

    for (int i = 0; i < 8; i++) {
        const int cur = i & 1;
        if (i < 7) {
            qkv_stage(smc, sb, cur ^ 1, x, r0, (i + 1) * 32);
            CP_COMMIT();
        }

        const uint32_t a_addr = a_base + cur * XSB;
        const uint32_t b_addr = b_base + cur * WTB;
        #pragma unroll
        for (int ks = 0; ks < 4; ks++) {
            uint32_t qa[4];
            ldsm4(qa, a_addr + ks * 32);
            #pragma unroll
            for (int np = 0; np < 12; np++) {
                uint32_t bb[4];
                ldsm4(bb, b_addr + np * (16 * WST * 4) + ks * 32);
                mma_tf32(c[2 * np],     qa, bb[0], bb[1]);
                mma_tf32(c[2 * np + 1], qa, bb[2], bb[3]);
            }
        }

        CP_WAIT0();
        __syncthreads();
    }

    const int pr = lane >> 2, pc = 2 * (lane & 3);
    const int row = r0 + wp * 16 + pr;
    const int bb_ = row >> 12;
    const int t_  = row & (T - 1);
    #pragma unroll
    for (int nt = 0; nt < 24; nt++) {
        int n = nt * 8 + pc;
        int m = n >> 6, h = n & 63;
        if (m == 2) {                       // V transposed, fp16
            uint16_t* vt = g_vt + ((size_t)bb_ * HP + h) * T + t_;
            vt[0]     = f2h(c[nt][0]);
            vt[T]     = f2h(c[nt][1]);
            vt[8]     = f2h(c[nt][2]);
            vt[T + 8] = f2h(c[nt][3]);
        } else {                            // Q (scale*log2e) / K packed bf16
            float s = (m == 0) ? (SCALE * LOG2E) : 1.f;
            uint16_t* dst = (m == 0) ? g_q : g_k;
            *(uint32_t*)(dst + (size_t)row * HP + h) =
                pack_bf2(c[nt][0] * s, c[nt][1] * s);
            *(uint32_t*)(dst + (size_t)(row + 8) * HP + h) =
                pack_bf2(c[nt][2] * s, c[nt][3] * s);
        }
    }
}

// ---------------------------------------------------------------------------
// Kernel 2: flash attention. S = QK^T bf16 m16n8k16; p = 2^S via ex2;
// PV = fp16 m16n8k16 (same 10-bit mantissa as tf32, 2x rate, no transpose:
// S C-frag pairs ARE fp16 A-frag pairs -> cvt.rn.f16x2 packs, zero shfl).
// smem: K bf16 2x[64][72], V^T fp16 2x[64][72] = 36864 B.
// ---------------------------------------------------------------------------
#define KSTB 144
#define KBUFB (64 * KSTB)        // 9216
#define VSTB 144
#define VBUF (64 * VSTB)         // 9216
#define KOFF 0
#define VOFF (2 * KBUFB)         // 18432
#define SMEMSZ (VOFF + 2 * VBUF) // 36864

__device__ __forceinline__ void load_kv(uint32_t ksm_b, uint32_t vsm_b, int buf,
                                        int t, int b) {
    const int tid = threadIdx.x;
    const uint16_t* kg  = g_k  + ((size_t)b * T + t * BN) * HP;
    const uint16_t* vtg = g_vt + (size_t)b * HP * T + t * BN;
    const uint32_t kdst = ksm_b + buf * KBUFB;
    const uint32_t vdst = vsm_b + buf * VBUF;
    #pragma unroll
    for (int j = 0; j < 4; j++) {
        int i = tid + j * 128;
        int n = i >> 3, c = i & 7;
        cpa16(kdst + n * KSTB + c * 16, kg + n * HP + c * 8);
    }
    #pragma unroll
    for (int j = 0; j < 4; j++) {
        int i = tid + j * 128;
        int n = i >> 3, c = i & 7;      // n = h row, c*8 = s offset (fp16)
        cpa16(vdst + n * VSTB + c * 16, vtg + (size_t)n * T + c * 8);
    }
}

__global__ void __launch_bounds__(128, 2) attn_tc(float* __restrict__ out) {
    extern __shared__ char smc[];
    const int tid  = threadIdx.x;
    const int lane = tid & 31;
    const int w    = tid >> 5;
    const int tig  = lane & 3;
    const int pr   = lane >> 2;

    const int b = blockIdx.x >> 5;
    const int row_blk = blockIdx.x * BM;

    const uint32_t ksm_b = smem_u32(smc + KOFF);
    const uint32_t vsm_b = smem_u32(smc + VOFF);
    const uint32_t kb_off = ((lane & 7) + 8 * (lane >> 4)) * KSTB
                          + ((lane >> 3) & 1) * 16;
    const uint32_t vb_off = ((lane & 7) + 8 * (lane >> 4)) * VSTB
                          + ((lane >> 3) & 1) * 16;

    // ---- stage Q (bf16) through K region, grab A-frags ----
    {
        const uint16_t* qb = g_q + (size_t)(row_blk + tid) * HP;
        char* dst = smc + tid * KSTB;
        #pragma unroll
        for (int j = 0; j < 8; j++)
            *(float4*)(dst + j * 16) = *(const float4*)(qb + j * 8);
    }
    __syncthreads();
    uint32_t qa[2][4][4];
    {
        const uint32_t a_addr = ksm_b
            + (w * 32 + (lane & 7) + 8 * ((lane >> 3) & 1)) * KSTB
            + (lane >> 4) * 16;
        #pragma unroll
        for (int msub = 0; msub < 2; msub++)
            #pragma unroll
            for (int kc = 0; kc < 4; kc++)
                ldsm4(qa[msub][kc], a_addr + msub * (16 * KSTB) + kc * 32);
    }
    __syncthreads();

    float z[2][7][4];
    #pragma unroll
    for (int i = 0; i < 2; i++)
        #pragma unroll
        for (int j = 0; j < 7; j++)
            #pragma unroll
            for (int e = 0; e < 4; e++) z[i][j][e] = 0.f;
    float lacc[2][2] = {{0.f, 0.f}, {0.f, 0.f}};

    load_kv(ksm_b, vsm_b, 0, 0, b);
    CP_COMMIT();
    CP_WAIT0();
    __syncthreads();

    for (int t = 0; t < NT; t++) {
        const int cur = t & 1;
        if (t + 1 < NT) load_kv(ksm_b, vsm_b, cur ^ 1, t + 1, b);
        CP_COMMIT();

        const uint32_t kb_addr = ksm_b + cur * KBUFB + kb_off;
        const uint32_t vb_addr = vsm_b + cur * VBUF + vb_off;

        // ---- S = Q K^T (bf16 k16) ----
        float sc[2][8][4];
        #pragma unroll
        for (int i = 0; i < 2; i++)
            #pragma unroll
            for (int j = 0; j < 8; j++)
                #pragma unroll
                for (int e = 0; e < 4; e++) sc[i][j][e] = 0.f;

        #pragma unroll
        for (int kc = 0; kc < 4; kc++) {
            #pragma unroll
            for (int nb = 0; nb < 4; nb++) {
                uint32_t bb[4];
                ldsm4(bb, kb_addr + nb * (16 * KSTB) + kc * 32);
                #pragma unroll
                for (int msub = 0; msub < 2; msub++) {
                    mma_bf16(sc[msub][2 * nb],     qa[msub][kc], bb[0], bb[1]);
                    mma_bf16(sc[msub][2 * nb + 1], qa[msub][kc], bb[2], bb[3]);
                }
            }
        }

        // ---- softmax p = 2^S, pack straight into fp16 A-frags ----
        // A-frag (m16n8k16) pair (pr, 2tig),(pr, 2tig+1) == S C-frag pair.
        uint32_t pp[2][4][4];
        #pragma unroll
        for (int msub = 0; msub < 2; msub++)
            #pragma unroll
            for (int kc = 0; kc < 4; kc++) {
                float p0 = ex2(sc[msub][2 * kc][0]);
                float p1 = ex2(sc[msub][2 * kc][1]);
                float p2 = ex2(sc[msub][2 * kc][2]);
                float p3 = ex2(sc[msub][2 * kc][3]);
                float p4 = ex2(sc[msub][2 * kc + 1][0]);
                float p5 = ex2(sc[msub][2 * kc + 1][1]);
                float p6 = ex2(sc[msub][2 * kc + 1][2]);
                float p7 = ex2(sc[msub][2 * kc + 1][3]);
                lacc[msub][0] += (p0 + p1) + (p4 + p5);
                lacc[msub][1] += (p2 + p3) + (p6 + p7);
                pp[msub][kc][0] = pack_h2(p0, p1);
                pp[msub][kc][1] = pack_h2(p2, p3);
                pp[msub][kc][2] = pack_h2(p4, p5);
                pp[msub][kc][3] = pack_h2(p6, p7);
            }

        // ---- Z += P V^T (fp16 m16n8k16) ----
        #pragma unroll
        for (int kc = 0; kc < 4; kc++) {
            #pragma unroll
            for (int np = 0; np < 4; np++) {
                uint32_t bb[4];
                ldsm4(bb, vb_addr + np * (16 * VSTB) + kc * 32);
                #pragma unroll
                for (int msub = 0; msub < 2; msub++) {
                    mma_f16(z[msub][2 * np], pp[msub][kc], bb[0], bb[1]);
                    if (np < 3)
                        mma_f16(z[msub][2 * np + 1], pp[msub][kc], bb[2], bb[3]);
                }
            }
        }

        CP_WAIT0();
        __syncthreads();
    }

    // ---- l reduction within quad; output ----
    #pragma unroll
    for (int msub = 0; msub < 2; msub++) {
        float l0 = lacc[msub][0], l1 = lacc[msub][1];
        l0 += __shfl_xor_sync(0xffffffffu, l0, 1);
        l0 += __shfl_xor_sync(0xffffffffu, l0, 2);
        l1 += __shfl_xor_sync(0xffffffffu, l1, 1);
        l1 += __shfl_xor_sync(0xffffffffu, l1, 2);
        const float il0 = 1.f / l0;
        const float il1 = 1.f / l1;

        const int pc = 2 * tig;
        const int m0 = row_blk + w * 32 + msub * 16 + pr;
        #pragma unroll
        for (int nt = 0; nt < 7; nt++) {
            int h = nt * 8 + pc;
            if (h <= 48) {
                *(float2*)(out + (size_t)m0 * H + h) =
                    make_float2(z[msub][nt][0] * il0, z[msub][nt][1] * il0);
                *(float2*)(out + (size_t)(m0 + 8) * H + h) =
                    make_float2(z[msub][nt][2] * il1, z[msub][nt][3] * il1);
            }
        }
    }
}

// ---------------------------------------------------------------------------
extern "C" void kernel_launch(void* const* d_in, const int* in_sizes, int n_in,
                              void* d_out, int out_size) {
    const float* x = (const float*)d_in[0];
    const float* w = (const float*)d_in[1];
    float* out = (float*)d_out;

    static int configured = 0;
    if (!configured) {
        cudaFuncSetAttribute(attn_tc, cudaFuncAttributeMaxDynamicSharedMemorySize, SMEMSZ);
        cudaFuncSetAttribute(qkv_mma, cudaFuncAttributeMaxDynamicSharedMemorySize, QSMEM);
        configured = 1;
    }

    wtrans<<<NQK, 256>>>(w);
    qkv_mma<<<(B * T) / 128, 256, QSMEM>>>(x);
    attn_tc<<<(B * T) / BM, 128, SMEMSZ>>>(out);
}